// round 8
// baseline (speedup 1.0000x reference)
#include <cuda_runtime.h>
#include <cuda_fp16.h>
#include <math.h>

typedef unsigned int u32;
typedef unsigned char u8;

// ---------------- static device scratch (allocation-free rule) ----------------
__device__ __align__(128) u8 g_xu[48*48*320];        // L1 input NHWC u8
__device__ __align__(128) u8 g_h0[96*96*192];        // L1 out / L2 in
__device__ __align__(128) u8 g_h1[192*192*192];      // L2 out / L3 in
__device__ __align__(128) u8 g_h2[384*384*192];      // L3 out / L4 in
__device__ __align__(128) char g_wt1[25*192*320];    // [tap][co][ci] s8
__device__ __align__(128) char g_wt2[25*192*192];
__device__ __align__(128) char g_wt3[25*192*192];
__device__ __align__(128) char g_wt4[9*16*192];      // [tap][n=(parity*4+co)][ci]
__device__ float g_b1q[192];
__device__ float g_b2q[192];
__device__ float g_b3q[192];
__device__ float g_b4q[3];
__device__ float g_params[24];

// ---------------- PTX wrappers ----------------
#define CPASYNC(dst, src, sz) \
    asm volatile("cp.async.cg.shared.global [%0], [%1], 16, %2;" :: "r"(dst), "l"(src), "r"(sz))
#define CPCOMMIT() asm volatile("cp.async.commit_group;")
#define CPWAIT(n)  asm volatile("cp.async.wait_group %0;" :: "n"(n))
#define LDSM4(r0,r1,r2,r3,addr) \
    asm volatile("ldmatrix.sync.aligned.m8n8.x4.shared.b16 {%0,%1,%2,%3}, [%4];" \
        : "=r"(r0),"=r"(r1),"=r"(r2),"=r"(r3) : "r"(addr))
#define IMMA16832(c0,c1,c2,c3,a0,a1,a2,a3,b0,b1) \
    asm volatile("mma.sync.aligned.m16n8k32.row.col.s32.u8.s8.s32 " \
        "{%0,%1,%2,%3}, {%4,%5,%6,%7}, {%8,%9}, {%0,%1,%2,%3};" \
        : "+r"(c0),"+r"(c1),"+r"(c2),"+r"(c3) \
        : "r"(a0),"r"(a1),"r"(a2),"r"(a3),"r"(b0),"r"(b1))

// ---------------- small prep kernels ----------------
__global__ void quant_biases(const float* __restrict__ b1, const float* __restrict__ b2,
                             const float* __restrict__ b3, const float* __restrict__ b4) {
    int i = threadIdx.x;
    if (i < 192) {
        g_b1q[i] = rintf(b1[i]);
        g_b2q[i] = rintf(b2[i]);
        g_b3q[i] = rintf(b3[i]);
    }
    if (i < 3) g_b4q[i] = rintf(b4[i]);
}

__global__ void prep_kernel(const float* __restrict__ relus,
                            const int* __restrict__ dvds,
                            const int* __restrict__ bitsp) {
    if (threadIdx.x == 0 && blockIdx.x == 0) {
        float B = bitsp ? (float)(*bitsp) : 8.0f;
        float maxv = exp2f(B) - 1.0f;
        const int sks[3] = {3, 4, 3};
        for (int i = 0; i < 3; i++) {
            float dv = (float)dvds[i];
            g_params[i*6+0] = exp2f(dv - 10.0f);
            g_params[i*6+1] = exp2f(9.0f - dv);
            g_params[i*6+2] = rintf((maxv / relus[i]) * 33554432.0f);
            float sk = (float)sks[i];
            g_params[i*6+3] = floorf((relus[i] + exp2f(sk - 1.0f)) * exp2f(-sk));
            g_params[i*6+4] = exp2f(24.0f - sk);
            g_params[i*6+5] = exp2f(sk - 25.0f);
        }
        float dv3 = (float)dvds[3];
        g_params[18] = exp2f(dv3 - 9.0f);
        g_params[19] = exp2f(8.0f - dv3);
    }
}

// NCHW f32 -> NHWC u8 (values are exact small non-negative ints)
__global__ void nchw2u8(const float* __restrict__ src, u8* __restrict__ dst,
                        int C, int HW) {
    int idx = blockIdx.x * blockDim.x + threadIdx.x;
    if (idx >= C * HW) return;
    int s = idx / C, c = idx % C;
    dst[idx] = (u8)__float2int_rn(src[c * HW + s]);
}

// w [CIN][COUT][5][5] f32 -> wt [tap][co][ci] s8, coalesced via smem transpose.
__global__ void prep_w(const float* __restrict__ w, char* __restrict__ wt,
                       int CIN, int COUT) {
    __shared__ float tile[320 * 25];
    const int co = blockIdx.x;
    const int tid = threadIdx.x;
    for (int i = tid; i < CIN * 25; i += 256) {
        int ci = i / 25, t = i % 25;
        tile[i] = w[((size_t)ci * COUT + co) * 25 + t];
    }
    __syncthreads();
    const int nc16 = CIN >> 4;
    for (int i = tid; i < 25 * nc16; i += 256) {
        int t = i / nc16, c16 = i % nc16;
        char h[16];
        #pragma unroll
        for (int j = 0; j < 16; j++) {
            float v = rintf(tile[(c16 * 16 + j) * 25 + t]);
            v = fminf(fmaxf(v, -128.f), 127.f);
            h[j] = (char)(int)v;
        }
        *(uint4*)(wt + ((size_t)t * COUT + co) * CIN + c16 * 16) = *(uint4*)h;
    }
}

// L4: w [192][3][5][5] -> wt4 [9][16][192] s8, n=(py*2+px)*4+co, zeros invalid/pad
__global__ void prep_w4(const float* __restrict__ w, char* __restrict__ wt) {
    int idx = blockIdx.x * blockDim.x + threadIdx.x;
    if (idx >= 9 * 16 * 192) return;
    int t = idx / (16 * 192);
    int r = idx % (16 * 192);
    int n = r / 192;
    int ci = r % 192;
    int dy = t / 3 - 1, dx = t % 3 - 1;
    int p = n >> 2, co = n & 3;
    int py = p >> 1, px = p & 1;
    float v = 0.f;
    if (co < 3 && (py == 0 || dy >= 0) && (px == 0 || dx >= 0)) {
        int ky = py + 2 - 2 * dy, kx = px + 2 - 2 * dx;
        v = rintf(w[((size_t)ci * 3 + co) * 25 + ky * 5 + kx]);
        v = fminf(fmaxf(v, -128.f), 127.f);
    }
    wt[idx] = (char)(int)v;
}

// ---------------- int8 tensor-core transposed conv ----------------
// CTA: (YR x 16) sites x NTILE output-n. 256 threads = 8 warps (WM x WN).
// K-chunk = 32 ci (imma m16n8k32 u8*s8+s32).
// A smem: [(YR+2) rows][18 cols][32 ci], site row (32B) padded to 48B. 2-stage ring.
// B smem: [NTILE n][32 ci], row padded to 48B. 4-stage ring, prefetch +3.
template<int NTILE, int WM, int WN, int YR, bool LAST>
__global__ void __launch_bounds__(256, 2) conv_mma(
    const u8* __restrict__ inA, void* __restrict__ outp,
    const char* __restrict__ Wt, const float* __restrict__ bq,
    const float* __restrict__ mul,
    int CIN, int COUT, int H, int W, int stage)
{
    constexpr int MI = YR / WM;
    constexpr int NI = NTILE / (8 * WN);
    constexpr int NPAIR = NI / 2;
    constexpr int NSITES = (YR + 2) * 18;
    constexpr int ASTG = NSITES * 48;
    constexpr int BSTG = NTILE * 48;
    __shared__ __align__(16) char smem[2 * ASTG + 4 * BSTG];

    const int tid = threadIdx.x;
    const int lane = tid & 31, wid = tid >> 5;
    const int warp_m = wid % WM, warp_n = wid / WM;
    const int x0 = blockIdx.x * 16, y0 = blockIdx.y * YR;
    int py, px, co0;
    if (LAST) { py = 0; px = 0; co0 = 0; }
    else { py = blockIdx.z & 1; px = (blockIdx.z >> 1) & 1; co0 = (blockIdx.z >> 2) * 64; }

    // tap tables
    int ntaps, tAoff[9], tBrow[9];
    if (LAST) {
        ntaps = 9;
        #pragma unroll
        for (int t = 0; t < 9; t++) { tAoff[t] = ((t / 3) * 18 + (t % 3)) * 48; tBrow[t] = t * 16; }
    } else {
        ntaps = 0;
        for (int dy = (py ? 0 : -1); dy <= 1; dy++)
            for (int dx = (px ? 0 : -1); dx <= 1; dx++) {
                tAoff[ntaps] = ((dy + 1) * 18 + (dx + 1)) * 48;
                tBrow[ntaps] = ((py + 2 - 2 * dy) * 5 + (px + 2 - 2 * dx)) * COUT + co0;
                ntaps++;
            }
    }
    const int nchunks = CIN >> 5;          // 32-ci chunks
    const int niter = nchunks * ntaps;

    const u32 smem_u = (u32)__cvta_generic_to_shared(smem);
    const u32 Abase = smem_u;
    const u32 Bbase = smem_u + 2 * ASTG;

    auto loadA = [&](int chunk, int slot) {
        const int ci0 = chunk << 5;
        #pragma unroll
        for (int k = 0; k < (NSITES * 2 + 255) / 256; k++) {
            int idx = tid + k * 256;
            if (idx < NSITES * 2) {
                int site = idx >> 1, seg = idx & 1;
                int r = site / 18, c = site % 18;
                int gy = y0 - 1 + r, gx = x0 - 1 + c;
                bool ok = (unsigned)gy < (unsigned)H && (unsigned)gx < (unsigned)W;
                const u8* src = ok ? (inA + ((size_t)(gy * W + gx) * CIN + ci0 + seg * 16)) : inA;
                u32 dst = Abase + slot * ASTG + site * 48 + seg * 16;
                CPASYNC(dst, src, ok ? 16 : 0);
            }
        }
    };
    auto loadB = [&](int tap, int chunk, int slot) {
        const int ci0 = chunk << 5;
        if (tid < NTILE * 2) {
            int n = tid >> 1, seg = tid & 1;
            const char* src = Wt + (size_t)(tBrow[tap] + n) * CIN + ci0 + seg * 16;
            u32 dst = Bbase + slot * BSTG + n * 48 + seg * 16;
            CPASYNC(dst, src, 16);
        }
    };

    // prologue: A(0), B(0..2) in 3 groups (ntaps >= 4 so iters 0..2 are chunk 0)
    loadA(0, 0); loadB(0, 0, 0); CPCOMMIT();
    loadB(1, 0, 1); CPCOMMIT();
    loadB(2, 0, 2); CPCOMMIT();

    int acc[MI][NI][4];
    #pragma unroll
    for (int mi = 0; mi < MI; mi++)
        #pragma unroll
        for (int ni = 0; ni < NI; ni++)
            #pragma unroll
            for (int k = 0; k < 4; k++) acc[mi][ni][k] = 0;

    // per-lane ldmatrix address offsets (identical geometry to f16 k16 case)
    const int la = lane & 7, ms = lane >> 3;
    const u32 aoff_lane = (u32)((la + ((ms & 1) << 3)) * 48 + ((ms >> 1) << 4));
    const u32 boff_lane = (u32)((la + ((lane >> 4) << 3)) * 48 + (((lane >> 3) & 1) << 4));

    int cur_tap = 0, cur_chunk = 0;
    int pf_tap = 3, pf_chunk = 0;   // metadata for iter i+3 (ntaps>=4)

    for (int i = 0; i < niter; i++) {
        CPWAIT(2);
        __syncthreads();
        // prefetch (after barrier: slot-cycle race-free)
        if (i + 3 < niter) loadB(pf_tap, pf_chunk, (i + 3) & 3);
        if (cur_tap == 0 && cur_chunk + 1 < nchunks) loadA(cur_chunk + 1, (cur_chunk + 1) & 1);
        CPCOMMIT();

        const u32 Astage = Abase + (cur_chunk & 1) * ASTG + tAoff[cur_tap] + aoff_lane;
        const u32 Bstage = Bbase + (i & 3) * BSTG + warp_n * (32 * 48) + boff_lane;

        u32 a[MI][4], b[NPAIR][4];
        #pragma unroll
        for (int mi = 0; mi < MI; mi++) {
            int ylocal = warp_m * MI + mi;
            LDSM4(a[mi][0], a[mi][1], a[mi][2], a[mi][3], Astage + ylocal * (18 * 48));
        }
        #pragma unroll
        for (int p2 = 0; p2 < NPAIR; p2++)
            LDSM4(b[p2][0], b[p2][1], b[p2][2], b[p2][3], Bstage + p2 * (16 * 48));

        #pragma unroll
        for (int mi = 0; mi < MI; mi++)
            #pragma unroll
            for (int ni = 0; ni < NI; ni++)
                IMMA16832(acc[mi][ni][0], acc[mi][ni][1], acc[mi][ni][2], acc[mi][ni][3],
                          a[mi][0], a[mi][1], a[mi][2], a[mi][3],
                          b[ni >> 1][(ni & 1) * 2], b[ni >> 1][(ni & 1) * 2 + 1]);

        if (++cur_tap == ntaps) { cur_tap = 0; cur_chunk++; }
        if (++pf_tap == ntaps) { pf_tap = 0; pf_chunk++; }
    }
    CPWAIT(0);

    // -------- quant epilogue --------
    float addA, invA, clpv = 0.f, sclv = 0.f, addB = 0.f, invB = 0.f;
    if (!LAST) {
        addA = g_params[stage*6+0]; invA = g_params[stage*6+1];
        clpv = g_params[stage*6+2]; sclv = g_params[stage*6+3];
        addB = g_params[stage*6+4]; invB = g_params[stage*6+5];
    } else {
        addA = g_params[18]; invA = g_params[19];
    }
    const int W2 = 2 * W;

    if (!LAST) {
        u8* out = (u8*)outp;
        #pragma unroll
        for (int mi = 0; mi < MI; mi++) {
            int ylocal = warp_m * MI + mi;
            int oy = 2 * (y0 + ylocal) + py;
            #pragma unroll
            for (int ni = 0; ni < NI; ni++) {
                int co = co0 + warp_n * 32 + ni * 8 + (lane & 3) * 2;
                float b0f = bq[co], b1f = bq[co + 1];
                float m0f = mul[co], m1f = mul[co + 1];
                #pragma unroll
                for (int h = 0; h < 2; h++) {
                    int xl = (lane >> 2) + h * 8;
                    int ox = 2 * (x0 + xl) + px;
                    float v0 = (float)acc[mi][ni][h * 2 + 0];
                    float v1 = (float)acc[mi][ni][h * 2 + 1];
                    v0 = floorf(((v0 + b0f) * m0f + addA) * invA);
                    v0 = fminf(fmaxf(v0, 0.f), clpv);
                    v0 = floorf((v0 * sclv + addB) * invB);
                    v1 = floorf(((v1 + b1f) * m1f + addA) * invA);
                    v1 = fminf(fmaxf(v1, 0.f), clpv);
                    v1 = floorf((v1 * sclv + addB) * invB);
                    unsigned short pk = (unsigned short)((u8)(int)v0 | (((u32)(u8)(int)v1) << 8));
                    *(unsigned short*)(out + ((size_t)oy * W2 + ox) * COUT + co) = pk;
                }
            }
        }
    } else {
        float* out = (float*)outp;
        const int PLANE = W2 * 2 * H;   // 768*768
        #pragma unroll
        for (int mi = 0; mi < MI; mi++) {
            int ylocal = warp_m * MI + mi;
            #pragma unroll
            for (int ni = 0; ni < NI; ni++) {
                int nbase = ni * 8 + (lane & 3) * 2;
                #pragma unroll
                for (int h = 0; h < 2; h++) {
                    int xl = (lane >> 2) + h * 8;
                    #pragma unroll
                    for (int j = 0; j < 2; j++) {
                        int n = nbase + j;
                        int p = n >> 2, c = n & 3;
                        if (c < 3) {
                            int pyy = p >> 1, pxx = p & 1;
                            int oy = 2 * (y0 + ylocal) + pyy;
                            int ox = 2 * (x0 + xl) + pxx;
                            float v = (float)acc[mi][ni][h * 2 + j];
                            v = (v + bq[c]) * mul[c];
                            v = floorf((v + addA) * invA);
                            out[(size_t)c * PLANE + (size_t)oy * W2 + ox] = v / 255.0f;
                        }
                    }
                }
            }
        }
    }
}

// ---------------- host launcher (graph-capturable: kernel launches only) -------
extern "C" void kernel_launch(void* const* d_in, const int* in_sizes, int n_in,
                              void* d_out, int out_size)
{
    const float* x     = (const float*)d_in[0];
    const float* w1    = (const float*)d_in[1];
    const float* b1    = (const float*)d_in[2];
    const float* w2    = (const float*)d_in[3];
    const float* b2    = (const float*)d_in[4];
    const float* w3    = (const float*)d_in[5];
    const float* b3    = (const float*)d_in[6];
    const float* w4    = (const float*)d_in[7];
    const float* b4    = (const float*)d_in[8];
    const float* m0    = (const float*)d_in[9];
    const float* m1    = (const float*)d_in[10];
    const float* m2    = (const float*)d_in[11];
    const float* m3    = (const float*)d_in[12];
    const float* relus = (const float*)d_in[13];
    const int*   dvds  = (const int*)d_in[14];
    const int*   bitsp = (n_in > 15) ? (const int*)d_in[15] : nullptr;

    u8 *xu, *h0, *h1, *h2;
    char *wt1, *wt2, *wt3, *wt4;
    float *b1q, *b2q, *b3q, *b4q;
    cudaGetSymbolAddress((void**)&xu,  g_xu);
    cudaGetSymbolAddress((void**)&h0,  g_h0);
    cudaGetSymbolAddress((void**)&h1,  g_h1);
    cudaGetSymbolAddress((void**)&h2,  g_h2);
    cudaGetSymbolAddress((void**)&wt1, g_wt1);
    cudaGetSymbolAddress((void**)&wt2, g_wt2);
    cudaGetSymbolAddress((void**)&wt3, g_wt3);
    cudaGetSymbolAddress((void**)&wt4, g_wt4);
    cudaGetSymbolAddress((void**)&b1q, g_b1q);
    cudaGetSymbolAddress((void**)&b2q, g_b2q);
    cudaGetSymbolAddress((void**)&b3q, g_b3q);
    cudaGetSymbolAddress((void**)&b4q, g_b4q);

    nchw2u8<<<(48*48*320 + 255)/256, 256>>>(x, xu, 320, 48*48);
    prep_w<<<192, 256>>>(w1, wt1, 320, 192);
    prep_w<<<192, 256>>>(w2, wt2, 192, 192);
    prep_w<<<192, 256>>>(w3, wt3, 192, 192);
    prep_w4<<<(9*16*192 + 255)/256, 256>>>(w4, wt4);
    quant_biases<<<1, 256>>>(b1, b2, b3, b4);
    prep_kernel<<<1, 1>>>(relus, dvds, bitsp);

    // L1: 320ch 48x48 -> 192ch 96x96
    conv_mma<64,4,2,8,false><<<dim3(3, 6, 12), 256>>>(xu, h0, wt1, b1q, m0, 320, 192, 48, 48, 0);
    // L2: 192ch 96x96 -> 192ch 192x192
    conv_mma<64,4,2,16,false><<<dim3(6, 6, 12), 256>>>(h0, h1, wt2, b2q, m1, 192, 192, 96, 96, 1);
    // L3: 192ch 192x192 -> 192ch 384x384
    conv_mma<64,4,2,16,false><<<dim3(12, 12, 12), 256>>>(h1, h2, wt3, b3q, m2, 192, 192, 192, 192, 2);
    // L4: 192ch 384x384 -> 3ch 768x768, parity-folded N=16, f32 NCHW out
    conv_mma<16,8,1,16,true><<<dim3(24, 24, 1), 256>>>(h2, d_out, wt4, b4q, m3, 192, 3, 384, 384, 3);
}

// round 9
// speedup vs baseline: 1.6442x; 1.6442x over previous
#include <cuda_runtime.h>
#include <cuda_fp16.h>
#include <math.h>

typedef unsigned int u32;

// ---------------- static device scratch (allocation-free rule) ----------------
__device__ __half g_xh[48*48*320];          // L1 input NHWC fp16
__device__ __half g_h0[96*96*192];          // L1 out / L2 in
__device__ __half g_h1[192*192*192];        // L2 out / L3 in
__device__ __half g_h2[384*384*192];        // L3 out / L4 in
__device__ __half g_wt1[25*192*320];        // [tap][co][ci]
__device__ __half g_wt2[25*192*192];
__device__ __half g_wt3[25*192*192];
__device__ __half g_wt4[9*16*192];          // [tap][n=(parity*4+co)][ci]
__device__ float g_b1q[192];
__device__ float g_b2q[192];
__device__ float g_b3q[192];
__device__ float g_b4q[3];
__device__ float g_params[24];

// ---------------- PTX wrappers ----------------
#define CPASYNC(dst, src, sz) \
    asm volatile("cp.async.cg.shared.global [%0], [%1], 16, %2;" :: "r"(dst), "l"(src), "r"(sz))
#define CPCOMMIT() asm volatile("cp.async.commit_group;")
#define CPWAIT(n)  asm volatile("cp.async.wait_group %0;" :: "n"(n))
#define LDSM4(r0,r1,r2,r3,addr) \
    asm volatile("ldmatrix.sync.aligned.m8n8.x4.shared.b16 {%0,%1,%2,%3}, [%4];" \
        : "=r"(r0),"=r"(r1),"=r"(r2),"=r"(r3) : "r"(addr))
#define MMA16816(c0,c1,c2,c3,a0,a1,a2,a3,b0,b1) \
    asm volatile("mma.sync.aligned.m16n8k16.row.col.f32.f16.f16.f32 " \
        "{%0,%1,%2,%3}, {%4,%5,%6,%7}, {%8,%9}, {%0,%1,%2,%3};" \
        : "+f"(c0),"+f"(c1),"+f"(c2),"+f"(c3) \
        : "r"(a0),"r"(a1),"r"(a2),"r"(a3),"r"(b0),"r"(b1))

// ---------------- small prep kernels ----------------
__global__ void quant_biases(const float* __restrict__ b1, const float* __restrict__ b2,
                             const float* __restrict__ b3, const float* __restrict__ b4) {
    int i = threadIdx.x;
    if (i < 192) {
        g_b1q[i] = rintf(b1[i]);
        g_b2q[i] = rintf(b2[i]);
        g_b3q[i] = rintf(b3[i]);
    }
    if (i < 3) g_b4q[i] = rintf(b4[i]);
}

__global__ void prep_kernel(const float* __restrict__ relus,
                            const int* __restrict__ dvds,
                            const int* __restrict__ bitsp) {
    if (threadIdx.x == 0 && blockIdx.x == 0) {
        float B = bitsp ? (float)(*bitsp) : 8.0f;
        float maxv = exp2f(B) - 1.0f;
        const int sks[3] = {3, 4, 3};
        for (int i = 0; i < 3; i++) {
            float dv = (float)dvds[i];
            g_params[i*6+0] = exp2f(dv - 10.0f);
            g_params[i*6+1] = exp2f(9.0f - dv);
            g_params[i*6+2] = rintf((maxv / relus[i]) * 33554432.0f);
            float sk = (float)sks[i];
            g_params[i*6+3] = floorf((relus[i] + exp2f(sk - 1.0f)) * exp2f(-sk));
            g_params[i*6+4] = exp2f(24.0f - sk);
            g_params[i*6+5] = exp2f(sk - 25.0f);
        }
        float dv3 = (float)dvds[3];
        g_params[18] = exp2f(dv3 - 9.0f);
        g_params[19] = exp2f(8.0f - dv3);
    }
}

// NCHW f32 -> NHWC fp16 (values are small ints: exact)
__global__ void nchw2nhwc(const float* __restrict__ src, __half* __restrict__ dst,
                          int C, int HW) {
    int idx = blockIdx.x * blockDim.x + threadIdx.x;
    if (idx >= C * HW) return;
    int s = idx / C, c = idx % C;
    dst[idx] = __float2half_rn(src[c * HW + s]);
}

// w [CIN][COUT][5][5] f32 -> wt [tap][co][ci] fp16, coalesced via smem transpose.
__global__ void prep_w(const float* __restrict__ w, __half* __restrict__ wt,
                       int CIN, int COUT) {
    __shared__ float tile[320 * 25];
    const int co = blockIdx.x;
    const int tid = threadIdx.x;
    for (int i = tid; i < CIN * 25; i += 256) {
        int ci = i / 25, t = i % 25;
        tile[i] = w[((size_t)ci * COUT + co) * 25 + t];
    }
    __syncthreads();
    const int nc8 = CIN >> 3;
    for (int i = tid; i < 25 * nc8; i += 256) {
        int t = i / nc8, c8 = i % nc8;
        __half h[8];
        #pragma unroll
        for (int j = 0; j < 8; j++)
            h[j] = __float2half_rn(rintf(tile[(c8 * 8 + j) * 25 + t]));
        *(uint4*)(wt + ((size_t)t * COUT + co) * CIN + c8 * 8) = *(uint4*)h;
    }
}

// L4: w [192][3][5][5] -> wt4 [9][16][192], n=(py*2+px)*4+co, zeros for invalid/pad
__global__ void prep_w4(const float* __restrict__ w, __half* __restrict__ wt) {
    int idx = blockIdx.x * blockDim.x + threadIdx.x;
    if (idx >= 9 * 16 * 192) return;
    int t = idx / (16 * 192);
    int r = idx % (16 * 192);
    int n = r / 192;
    int ci = r % 192;
    int dy = t / 3 - 1, dx = t % 3 - 1;
    int p = n >> 2, co = n & 3;
    int py = p >> 1, px = p & 1;
    float v = 0.f;
    if (co < 3 && (py == 0 || dy >= 0) && (px == 0 || dx >= 0)) {
        int ky = py + 2 - 2 * dy, kx = px + 2 - 2 * dx;
        v = rintf(w[((size_t)ci * 3 + co) * 25 + ky * 5 + kx]);
    }
    wt[idx] = __float2half_rn(v);
}

// ---------------- tensor-core transposed conv ----------------
// CTA: (YR x XW) sites x NTILE output-n. THREADS = WM*WN*32.
// m16 tile = 16 consecutive x-sites of one y-row; Mtiles = YR*(XW/16).
// A smem: [(YR+2) rows][XW+2 cols][16 ci], site row padded to 48B. 2-stage ring.
// B smem: [NTILE n][16 ci], row padded to 48B. 4-stage ring, prefetch +3.
template<int XW, int NTILE, int WM, int WN, int YR, bool LAST>
__global__ void __launch_bounds__(WM*WN*32, 512/(WM*WN*32)) conv_mma(
    const __half* __restrict__ inA, void* __restrict__ outp,
    const __half* __restrict__ Wt, const float* __restrict__ bq,
    const float* __restrict__ mul,
    int CIN, int COUT, int H, int W, int stage)
{
    constexpr int THREADS = WM * WN * 32;
    constexpr int XH = XW / 16;
    constexpr int MTILES = YR * XH;
    constexpr int MI = MTILES / WM;
    constexpr int NI = NTILE / (8 * WN);
    constexpr int NPAIR = NI / 2;
    constexpr int COLS = XW + 2;
    constexpr int NSITES = (YR + 2) * COLS;
    constexpr int ASTG = NSITES * 48;
    constexpr int BSTG = NTILE * 48;
    extern __shared__ __align__(16) char smem[];

    const int tid = threadIdx.x;
    const int lane = tid & 31, wid = tid >> 5;
    const int warp_m = wid % WM, warp_n = wid / WM;
    const int x0 = blockIdx.x * XW, y0 = blockIdx.y * YR;
    int py, px, co0;
    if (LAST) { py = 0; px = 0; co0 = 0; }
    else { py = blockIdx.z & 1; px = (blockIdx.z >> 1) & 1; co0 = (blockIdx.z >> 2) * 64; }

    // tap tables
    int ntaps, tAoff[9], tBrow[9];
    if (LAST) {
        ntaps = 9;
        #pragma unroll
        for (int t = 0; t < 9; t++) { tAoff[t] = ((t / 3) * COLS + (t % 3)) * 48; tBrow[t] = t * 16; }
    } else {
        ntaps = 0;
        for (int dy = (py ? 0 : -1); dy <= 1; dy++)
            for (int dx = (px ? 0 : -1); dx <= 1; dx++) {
                tAoff[ntaps] = ((dy + 1) * COLS + (dx + 1)) * 48;
                tBrow[ntaps] = ((py + 2 - 2 * dy) * 5 + (px + 2 - 2 * dx)) * COUT + co0;
                ntaps++;
            }
    }
    const int nchunks = CIN >> 4;
    const int niter = nchunks * ntaps;

    const u32 smem_u = (u32)__cvta_generic_to_shared(smem);
    const u32 Abase = smem_u;
    const u32 Bbase = smem_u + 2 * ASTG;

    auto loadA = [&](int chunk, int slot) {
        const int ci0 = chunk << 4;
        #pragma unroll
        for (int k = 0; k < (NSITES * 2 + THREADS - 1) / THREADS; k++) {
            int idx = tid + k * THREADS;
            if (idx < NSITES * 2) {
                int site = idx >> 1, seg = idx & 1;
                int r = site / COLS, c = site % COLS;
                int gy = y0 - 1 + r, gx = x0 - 1 + c;
                bool ok = (unsigned)gy < (unsigned)H && (unsigned)gx < (unsigned)W;
                const __half* src = ok ? (inA + ((size_t)(gy * W + gx) * CIN + ci0 + seg * 8)) : inA;
                u32 dst = Abase + slot * ASTG + site * 48 + seg * 16;
                CPASYNC(dst, src, ok ? 16 : 0);
            }
        }
    };
    auto loadB = [&](int tap, int chunk, int slot) {
        const int ci0 = chunk << 4;
        if (tid < NTILE * 2) {
            int n = tid >> 1, seg = tid & 1;
            const __half* src = Wt + (size_t)(tBrow[tap] + n) * CIN + ci0 + seg * 8;
            u32 dst = Bbase + slot * BSTG + n * 48 + seg * 16;
            CPASYNC(dst, src, 16);
        }
    };

    // prologue: A(0), B(0..2) in 3 groups (ntaps >= 4 so iters 0..2 are chunk 0)
    loadA(0, 0); loadB(0, 0, 0); CPCOMMIT();
    loadB(1, 0, 1); CPCOMMIT();
    loadB(2, 0, 2); CPCOMMIT();

    float acc[MI][NI][4];
    #pragma unroll
    for (int mi = 0; mi < MI; mi++)
        #pragma unroll
        for (int ni = 0; ni < NI; ni++)
            #pragma unroll
            for (int k = 0; k < 4; k++) acc[mi][ni][k] = 0.f;

    // per-lane ldmatrix address offsets
    const int la = lane & 7, ms = lane >> 3;
    const u32 aoff_lane = (u32)((la + ((ms & 1) << 3)) * 48 + ((ms >> 1) << 4));
    const u32 boff_lane = (u32)((la + ((lane >> 4) << 3)) * 48 + (((lane >> 3) & 1) << 4));

    int cur_tap = 0, cur_chunk = 0;
    int pf_tap = 3, pf_chunk = 0;   // metadata for iter i+3 (ntaps>=4)

    for (int i = 0; i < niter; i++) {
        CPWAIT(2);
        __syncthreads();
        // prefetch (after barrier: slot-cycle race-free)
        if (i + 3 < niter) loadB(pf_tap, pf_chunk, (i + 3) & 3);
        if (cur_tap == 0 && cur_chunk + 1 < nchunks) loadA(cur_chunk + 1, (cur_chunk + 1) & 1);
        CPCOMMIT();

        const u32 Astage = Abase + (cur_chunk & 1) * ASTG + tAoff[cur_tap] + aoff_lane;
        const u32 Bstage = Bbase + (i & 3) * BSTG + warp_n * (NI * 8 * 48) + boff_lane;

        u32 a[MI][4], b[NPAIR][4];
        #pragma unroll
        for (int mi = 0; mi < MI; mi++) {
            int mt = warp_m * MI + mi;
            int ylocal = mt / XH, xh = mt % XH;
            LDSM4(a[mi][0], a[mi][1], a[mi][2], a[mi][3],
                  Astage + (ylocal * COLS + xh * 16) * 48);
        }
        #pragma unroll
        for (int p2 = 0; p2 < NPAIR; p2++)
            LDSM4(b[p2][0], b[p2][1], b[p2][2], b[p2][3], Bstage + p2 * (16 * 48));

        #pragma unroll
        for (int mi = 0; mi < MI; mi++)
            #pragma unroll
            for (int ni = 0; ni < NI; ni++)
                MMA16816(acc[mi][ni][0], acc[mi][ni][1], acc[mi][ni][2], acc[mi][ni][3],
                         a[mi][0], a[mi][1], a[mi][2], a[mi][3],
                         b[ni >> 1][(ni & 1) * 2], b[ni >> 1][(ni & 1) * 2 + 1]);

        if (++cur_tap == ntaps) { cur_tap = 0; cur_chunk++; }
        if (++pf_tap == ntaps) { pf_tap = 0; pf_chunk++; }
    }
    CPWAIT(0);

    // -------- quant epilogue --------
    float addA, invA, clpv = 0.f, sclv = 0.f, addB = 0.f, invB = 0.f;
    if (!LAST) {
        addA = g_params[stage*6+0]; invA = g_params[stage*6+1];
        clpv = g_params[stage*6+2]; sclv = g_params[stage*6+3];
        addB = g_params[stage*6+4]; invB = g_params[stage*6+5];
    } else {
        addA = g_params[18]; invA = g_params[19];
    }
    const int W2 = 2 * W;

    if (!LAST) {
        __half* out = (__half*)outp;
        #pragma unroll
        for (int mi = 0; mi < MI; mi++) {
            int mt = warp_m * MI + mi;
            int ylocal = mt / XH, xh = mt % XH;
            int oy = 2 * (y0 + ylocal) + py;
            #pragma unroll
            for (int ni = 0; ni < NI; ni++) {
                int co = co0 + warp_n * (NI * 8) + ni * 8 + (lane & 3) * 2;
                float b0f = bq[co], b1f = bq[co + 1];
                float m0f = mul[co], m1f = mul[co + 1];
                #pragma unroll
                for (int h = 0; h < 2; h++) {
                    int xl = (lane >> 2) + h * 8 + xh * 16;
                    int ox = 2 * (x0 + xl) + px;
                    float v0 = acc[mi][ni][h * 2 + 0];
                    float v1 = acc[mi][ni][h * 2 + 1];
                    v0 = floorf(((v0 + b0f) * m0f + addA) * invA);
                    v0 = fminf(fmaxf(v0, 0.f), clpv);
                    v0 = floorf((v0 * sclv + addB) * invB);
                    v1 = floorf(((v1 + b1f) * m1f + addA) * invA);
                    v1 = fminf(fmaxf(v1, 0.f), clpv);
                    v1 = floorf((v1 * sclv + addB) * invB);
                    __half2 hv = __floats2half2_rn(v0, v1);
                    *(__half2*)(out + ((size_t)oy * W2 + ox) * COUT + co) = hv;
                }
            }
        }
    } else {
        float* out = (float*)outp;
        const int PLANE = W2 * 2 * H;   // 768*768
        #pragma unroll
        for (int mi = 0; mi < MI; mi++) {
            int mt = warp_m * MI + mi;
            int ylocal = mt / XH, xh = mt % XH;
            #pragma unroll
            for (int ni = 0; ni < NI; ni++) {
                int nbase = ni * 8 + (lane & 3) * 2;
                #pragma unroll
                for (int h = 0; h < 2; h++) {
                    int xl = (lane >> 2) + h * 8 + xh * 16;
                    #pragma unroll
                    for (int j = 0; j < 2; j++) {
                        int n = nbase + j;
                        int p = n >> 2, c = n & 3;
                        if (c < 3) {
                            int pyy = p >> 1, pxx = p & 1;
                            int oy = 2 * (y0 + ylocal) + pyy;
                            int ox = 2 * (x0 + xl) + pxx;
                            float v = acc[mi][ni][h * 2 + j];
                            v = (v + bq[c]) * mul[c];
                            v = floorf((v + addA) * invA);
                            out[(size_t)c * PLANE + (size_t)oy * W2 + ox] = v / 255.0f;
                        }
                    }
                }
            }
        }
    }
}

// ---------------- host launcher (graph-capturable: kernel launches only) -------
extern "C" void kernel_launch(void* const* d_in, const int* in_sizes, int n_in,
                              void* d_out, int out_size)
{
    const float* x     = (const float*)d_in[0];
    const float* w1    = (const float*)d_in[1];
    const float* b1    = (const float*)d_in[2];
    const float* w2    = (const float*)d_in[3];
    const float* b2    = (const float*)d_in[4];
    const float* w3    = (const float*)d_in[5];
    const float* b3    = (const float*)d_in[6];
    const float* w4    = (const float*)d_in[7];
    const float* b4    = (const float*)d_in[8];
    const float* m0    = (const float*)d_in[9];
    const float* m1    = (const float*)d_in[10];
    const float* m2    = (const float*)d_in[11];
    const float* m3    = (const float*)d_in[12];
    const float* relus = (const float*)d_in[13];
    const int*   dvds  = (const int*)d_in[14];
    const int*   bitsp = (n_in > 15) ? (const int*)d_in[15] : nullptr;

    __half *xh, *h0, *h1, *h2, *wt1, *wt2, *wt3, *wt4;
    float *b1q, *b2q, *b3q, *b4q;
    cudaGetSymbolAddress((void**)&xh,  g_xh);
    cudaGetSymbolAddress((void**)&h0,  g_h0);
    cudaGetSymbolAddress((void**)&h1,  g_h1);
    cudaGetSymbolAddress((void**)&h2,  g_h2);
    cudaGetSymbolAddress((void**)&wt1, g_wt1);
    cudaGetSymbolAddress((void**)&wt2, g_wt2);
    cudaGetSymbolAddress((void**)&wt3, g_wt3);
    cudaGetSymbolAddress((void**)&wt4, g_wt4);
    cudaGetSymbolAddress((void**)&b1q, g_b1q);
    cudaGetSymbolAddress((void**)&b2q, g_b2q);
    cudaGetSymbolAddress((void**)&b3q, g_b3q);
    cudaGetSymbolAddress((void**)&b4q, g_b4q);

    nchw2nhwc<<<(48*48*320 + 255)/256, 256>>>(x, xh, 320, 48*48);
    prep_w<<<192, 256>>>(w1, wt1, 320, 192);
    prep_w<<<192, 256>>>(w2, wt2, 192, 192);
    prep_w<<<192, 256>>>(w3, wt3, 192, 192);
    prep_w4<<<(9*16*192 + 255)/256, 256>>>(w4, wt4);
    quant_biases<<<1, 256>>>(b1, b2, b3, b4);
    prep_kernel<<<1, 1>>>(relus, dvds, bitsp);

    // dynamic smem sizes: 2*ASTG + 4*BSTG
    const int SM_L1 = 2 * (10 * 18 * 48) + 4 * (64 * 48);   // 29568
    const int SM_W  = 2 * (18 * 34 * 48) + 4 * (64 * 48);   // 71040
    const int SM_L4 = 2 * (18 * 34 * 48) + 4 * (16 * 48);   // 61824

    auto kL1 = conv_mma<16,64,4,2,8,false>;
    auto kW  = conv_mma<32,64,16,1,16,false>;
    auto kL4 = conv_mma<32,16,16,1,16,true>;
    cudaFuncSetAttribute(kL1, cudaFuncAttributeMaxDynamicSharedMemorySize, SM_L1);
    cudaFuncSetAttribute(kW,  cudaFuncAttributeMaxDynamicSharedMemorySize, SM_W);
    cudaFuncSetAttribute(kL4, cudaFuncAttributeMaxDynamicSharedMemorySize, SM_L4);

    // L1: 320ch 48x48 -> 192ch 96x96 (narrow tile, 256 thr, 2 CTA/SM)
    kL1<<<dim3(3, 6, 12), 256, SM_L1>>>(xh, h0, wt1, b1q, m0, 320, 192, 48, 48, 0);
    // L2: 192ch 96x96 -> 192ch 192x192 (wide tile, 512 thr)
    kW<<<dim3(3, 6, 12), 512, SM_W>>>(h0, h1, wt2, b2q, m1, 192, 192, 96, 96, 1);
    // L3: 192ch 192x192 -> 192ch 384x384
    kW<<<dim3(6, 12, 12), 512, SM_W>>>(h1, h2, wt3, b3q, m2, 192, 192, 192, 192, 2);
    // L4: 192ch 384x384 -> 3ch 768x768, parity-folded N=16, f32 NCHW out
    kL4<<<dim3(12, 24, 1), 512, SM_L4>>>(h2, d_out, wt4, b4q, m3, 192, 3, 384, 384, 3);
}